// round 1
// baseline (speedup 1.0000x reference)
#include <cuda_runtime.h>
#include <cstdint>

// Problem constants
#define B 8
#define S 2048
#define DIN 768
#define DH 64
#define NROWS (B*S)   // 16384

// Scratch for projected q (normalized & pre-scaled), k (normalized), v
__device__ float g_q[NROWS*DH];
__device__ float g_k[NROWS*DH];
__device__ float g_v[NROWS*DH];

typedef unsigned long long u64;

// ---- packed f32x2 helpers (sm_100+/sm_103a) ----
__device__ __forceinline__ void fma2(u64 &d, u64 a, u64 b) {
    asm("fma.rn.f32x2 %0, %1, %2, %0;" : "+l"(d) : "l"(a), "l"(b));
}
__device__ __forceinline__ u64 add2(u64 a, u64 b) {
    u64 r; asm("add.rn.f32x2 %0, %1, %2;" : "=l"(r) : "l"(a), "l"(b)); return r;
}
__device__ __forceinline__ u64 pack2(float lo, float hi) {
    u64 r; asm("mov.b64 %0, {%1, %2};" : "=l"(r) : "f"(lo), "f"(hi)); return r;
}
__device__ __forceinline__ float2 unpack2(u64 v) {
    float2 f; asm("mov.b64 {%0, %1}, %2;" : "=f"(f.x), "=f"(f.y) : "l"(v)); return f;
}
// 16B shared load -> two packed f32x2 regs. volatile: address is kt-invariant,
// content is not — must not be CSE'd/hoisted across __syncthreads.
__device__ __forceinline__ void lds_f4_u64(u64 &a, u64 &b, uint32_t addr) {
    asm volatile("ld.shared.v2.u64 {%0, %1}, [%2];" : "=l"(a), "=l"(b) : "r"(addr));
}

// ============================================================
// Projection: out[row, 0..63] = X[row,:] @ W + b, fused epilogue:
//   which==0 (q): row /= ||row||, * 0.125 (folds 1/sqrt(64) attention scale)
//   which==1 (k): row /= ||row||
//   which==2 (v): as-is
// Block: 128 threads, one row per thread. W k-chunked through smem (broadcast reads).
// ============================================================
__global__ __launch_bounds__(128) void proj_kernel(
    const float* __restrict__ Xq, const float* __restrict__ Xk, const float* __restrict__ Xv,
    const float* __restrict__ Wq, const float* __restrict__ bq,
    const float* __restrict__ Wk, const float* __restrict__ bk,
    const float* __restrict__ Wv, const float* __restrict__ bv)
{
    __shared__ float4 Ws[64*16];   // 64 k-rows x 64 cols (16KB)
    const int which = blockIdx.y;
    const float* X; const float* W; const float* bias; float* out;
    if (which == 0)      { X = Xq; W = Wq; bias = bq; out = g_q; }
    else if (which == 1) { X = Xk; W = Wk; bias = bk; out = g_k; }
    else                 { X = Xv; W = Wv; bias = bv; out = g_v; }

    const int tid = threadIdx.x;
    const long row = (long)blockIdx.x * 128 + tid;

    u64 acc[32];
    #pragma unroll
    for (int j = 0; j < 32; j++) acc[j] = pack2(bias[2*j], bias[2*j+1]);

    const float* xrow = X + row * DIN;
    const uint32_t ws_addr = (uint32_t)__cvta_generic_to_shared(Ws);

    for (int k0 = 0; k0 < DIN; k0 += 64) {
        __syncthreads();
        const float4* Wg = (const float4*)(W + (long)k0 * DH);
        #pragma unroll
        for (int i = 0; i < 8; i++) Ws[tid + i*128] = Wg[tid + i*128];
        __syncthreads();

        #pragma unroll 4
        for (int kk = 0; kk < 64; kk += 4) {
            float4 x4 = *(const float4*)(xrow + k0 + kk);
            float xs[4] = {x4.x, x4.y, x4.z, x4.w};
            #pragma unroll
            for (int u = 0; u < 4; u++) {
                u64 xx = pack2(xs[u], xs[u]);
                uint32_t wrow = ws_addr + (uint32_t)(kk + u) * 256;  // 16 float4 per k-row
                #pragma unroll
                for (int d = 0; d < 16; d++) {
                    u64 wa, wb;
                    lds_f4_u64(wa, wb, wrow + d*16);
                    fma2(acc[2*d],   xx, wa);
                    fma2(acc[2*d+1], xx, wb);
                }
            }
        }
    }

    // epilogue: unpack, optional L2 normalize (+scale for q), store
    float res[64];
    float ss = 0.f;
    #pragma unroll
    for (int j = 0; j < 32; j++) {
        float2 f = unpack2(acc[j]);
        res[2*j] = f.x; res[2*j+1] = f.y;
        ss += f.x*f.x + f.y*f.y;
    }
    float scale = 1.0f;
    if (which == 0)      scale = rsqrtf(ss) * 0.125f;
    else if (which == 1) scale = rsqrtf(ss);

    float4* orow = (float4*)(out + row * DH);
    #pragma unroll
    for (int j4 = 0; j4 < 16; j4++) {
        float4 o;
        o.x = res[4*j4+0]*scale; o.y = res[4*j4+1]*scale;
        o.z = res[4*j4+2]*scale; o.w = res[4*j4+3]*scale;
        orow[j4] = o;
    }
}

// ============================================================
// Attention: per (batch, 128-query tile) block, 128 threads, 1 query row/thread.
// Scores bounded in [-0.125, 0.125] (cosine attention) -> NO max subtraction
// needed: p = exp(s) directly, l = sum p, out = (sum p*v) / l.
// K/V streamed through smem in 64-key tiles (broadcast reads).
// ============================================================
__global__ __launch_bounds__(128) void attn_kernel(float* __restrict__ out)
{
    __shared__ float4 Ks[64*16];   // 16KB
    __shared__ float4 Vs[64*16];   // 16KB

    const int tid = threadIdx.x;
    const int b = blockIdx.y;
    const int row = blockIdx.x * 128 + tid;        // within batch
    const long gq = (long)b * S * DH + (long)row * DH;

    // load q row (already normalized & pre-scaled) into packed regs
    u64 q2[32];
    {
        const float4* qrow = (const float4*)(g_q + gq);
        #pragma unroll
        for (int i = 0; i < 16; i++) {
            float4 f = qrow[i];
            q2[2*i]   = pack2(f.x, f.y);
            q2[2*i+1] = pack2(f.z, f.w);
        }
    }
    u64 o2[32];
    #pragma unroll
    for (int i = 0; i < 32; i++) o2[i] = 0ull;
    float l = 0.f;

    const float4* Kg = (const float4*)(g_k + (long)b * S * DH);
    const float4* Vg = (const float4*)(g_v + (long)b * S * DH);
    const uint32_t ks_addr = (uint32_t)__cvta_generic_to_shared(Ks);
    const uint32_t vs_addr = (uint32_t)__cvta_generic_to_shared(Vs);

    for (int kt = 0; kt < S; kt += 64) {
        __syncthreads();
        #pragma unroll
        for (int i = 0; i < 8; i++) {
            Ks[tid + i*128] = Kg[kt*16 + tid + i*128];
            Vs[tid + i*128] = Vg[kt*16 + tid + i*128];
        }
        __syncthreads();

        #pragma unroll 4
        for (int j = 0; j < 64; j++) {
            // s = q . k_j   (4 packed accumulators to break the dep chain)
            u64 a0 = 0ull, a1 = 0ull, a2 = 0ull, a3 = 0ull;
            const uint32_t krow = ks_addr + (uint32_t)j * 256;
            #pragma unroll
            for (int d = 0; d < 16; d += 2) {
                u64 ka, kb, kc, kd;
                lds_f4_u64(ka, kb, krow + d*16);
                lds_f4_u64(kc, kd, krow + d*16 + 16);
                fma2(a0, q2[2*d],   ka);
                fma2(a1, q2[2*d+1], kb);
                fma2(a2, q2[2*d+2], kc);
                fma2(a3, q2[2*d+3], kd);
            }
            float2 sf = unpack2(add2(add2(a0, a1), add2(a2, a3)));
            float p = __expf(sf.x + sf.y);
            l += p;
            u64 p2 = pack2(p, p);

            const uint32_t vrow = vs_addr + (uint32_t)j * 256;
            #pragma unroll
            for (int d = 0; d < 16; d++) {
                u64 va, vb;
                lds_f4_u64(va, vb, vrow + d*16);
                fma2(o2[2*d],   p2, va);
                fma2(o2[2*d+1], p2, vb);
            }
        }
    }

    const float inv = 1.0f / l;
    float4* orow = (float4*)(out + gq);
    #pragma unroll
    for (int i = 0; i < 16; i++) {
        float2 f0 = unpack2(o2[2*i]);
        float2 f1 = unpack2(o2[2*i+1]);
        float4 o;
        o.x = f0.x * inv; o.y = f0.y * inv;
        o.z = f1.x * inv; o.w = f1.y * inv;
        orow[i] = o;
    }
}

// ============================================================
extern "C" void kernel_launch(void* const* d_in, const int* in_sizes, int n_in,
                              void* d_out, int out_size)
{
    const float* query = (const float*)d_in[0];
    const float* key   = (const float*)d_in[1];
    const float* value = (const float*)d_in[2];
    const float* Wq    = (const float*)d_in[3];
    const float* bq    = (const float*)d_in[4];
    const float* Wk    = (const float*)d_in[5];
    const float* bk    = (const float*)d_in[6];
    const float* Wv    = (const float*)d_in[7];
    const float* bv    = (const float*)d_in[8];
    float* out = (float*)d_out;

    dim3 pgrid(NROWS / 128, 3);
    proj_kernel<<<pgrid, 128>>>(query, key, value, Wq, bq, Wk, bk, Wv, bv);

    dim3 agrid(S / 128, B);
    attn_kernel<<<agrid, 128>>>(out);
}

// round 2
// speedup vs baseline: 1.1381x; 1.1381x over previous
#include <cuda_runtime.h>
#include <cstdint>

// Problem constants
#define B 8
#define S 2048
#define DIN 768
#define DH 64
#define NROWS (B*S)      // 16384
#define KSPLIT 8
#define KEYS_PER_SPLIT (S/KSPLIT)   // 256
#define KTILE 64
#define TQ 64            // queries per attn CTA

// Scratch: projected q (normalized, pre-scaled by 0.125), k (normalized), v
__device__ float g_q[NROWS*DH];
__device__ float g_k[NROWS*DH];
__device__ float g_v[NROWS*DH];
// Split-K partials: unnormalized o and row sums l
__device__ float g_opart[KSPLIT*NROWS*DH];   // 32 MB
__device__ float g_lpart[KSPLIT*NROWS];      // 512 KB

typedef unsigned long long u64;

// ---- packed f32x2 helpers (sm_103a) ----
__device__ __forceinline__ void fma2(u64 &d, u64 a, u64 b) {
    asm("fma.rn.f32x2 %0, %1, %2, %0;" : "+l"(d) : "l"(a), "l"(b));
}
__device__ __forceinline__ u64 add2(u64 a, u64 b) {
    u64 r; asm("add.rn.f32x2 %0, %1, %2;" : "=l"(r) : "l"(a), "l"(b)); return r;
}
__device__ __forceinline__ u64 pack2(float lo, float hi) {
    u64 r; asm("mov.b64 %0, {%1, %2};" : "=l"(r) : "f"(lo), "f"(hi)); return r;
}
__device__ __forceinline__ float2 unpack2(u64 v) {
    float2 f; asm("mov.b64 {%0, %1}, %2;" : "=f"(f.x), "=f"(f.y) : "l"(v)); return f;
}
// 16B shared load -> two packed f32x2 regs. volatile: address loop-invariant,
// content changes across __syncthreads.
__device__ __forceinline__ void lds_f4_u64(u64 &a, u64 &b, uint32_t addr) {
    asm volatile("ld.shared.v2.u64 {%0, %1}, [%2];" : "=l"(a), "=l"(b) : "r"(addr));
}

// ============================================================
// Projection (unchanged structurally): out = X@W + b, fused epilogue
//   which 0 (q): /||.|| * 0.125;  1 (k): /||.||;  2 (v): raw
// ============================================================
__global__ __launch_bounds__(128) void proj_kernel(
    const float* __restrict__ Xq, const float* __restrict__ Xk, const float* __restrict__ Xv,
    const float* __restrict__ Wq, const float* __restrict__ bq,
    const float* __restrict__ Wk, const float* __restrict__ bk,
    const float* __restrict__ Wv, const float* __restrict__ bv)
{
    __shared__ float4 Ws[64*16];
    const int which = blockIdx.y;
    const float* X; const float* W; const float* bias; float* out;
    if (which == 0)      { X = Xq; W = Wq; bias = bq; out = g_q; }
    else if (which == 1) { X = Xk; W = Wk; bias = bk; out = g_k; }
    else                 { X = Xv; W = Wv; bias = bv; out = g_v; }

    const int tid = threadIdx.x;
    const long row = (long)blockIdx.x * 128 + tid;

    u64 acc[32];
    #pragma unroll
    for (int j = 0; j < 32; j++) acc[j] = pack2(bias[2*j], bias[2*j+1]);

    const float* xrow = X + row * DIN;
    const uint32_t ws_addr = (uint32_t)__cvta_generic_to_shared(Ws);

    for (int k0 = 0; k0 < DIN; k0 += 64) {
        __syncthreads();
        const float4* Wg = (const float4*)(W + (long)k0 * DH);
        #pragma unroll
        for (int i = 0; i < 8; i++) Ws[tid + i*128] = Wg[tid + i*128];
        __syncthreads();

        #pragma unroll 4
        for (int kk = 0; kk < 64; kk += 4) {
            float4 x4 = *(const float4*)(xrow + k0 + kk);
            float xs[4] = {x4.x, x4.y, x4.z, x4.w};
            #pragma unroll
            for (int u = 0; u < 4; u++) {
                u64 xx = pack2(xs[u], xs[u]);
                uint32_t wrow = ws_addr + (uint32_t)(kk + u) * 256;
                #pragma unroll
                for (int d = 0; d < 16; d++) {
                    u64 wa, wb;
                    lds_f4_u64(wa, wb, wrow + d*16);
                    fma2(acc[2*d],   xx, wa);
                    fma2(acc[2*d+1], xx, wb);
                }
            }
        }
    }

    float res[64];
    float ss = 0.f;
    #pragma unroll
    for (int j = 0; j < 32; j++) {
        float2 f = unpack2(acc[j]);
        res[2*j] = f.x; res[2*j+1] = f.y;
        ss += f.x*f.x + f.y*f.y;
    }
    float scale = 1.0f;
    if (which == 0)      scale = rsqrtf(ss) * 0.125f;
    else if (which == 1) scale = rsqrtf(ss);

    float4* orow = (float4*)(out + row * DH);
    #pragma unroll
    for (int j4 = 0; j4 < 16; j4++) {
        float4 o;
        o.x = res[4*j4+0]*scale; o.y = res[4*j4+1]*scale;
        o.z = res[4*j4+2]*scale; o.w = res[4*j4+3]*scale;
        orow[j4] = o;
    }
}

// ============================================================
// Attention pass 1 (split-K): CTA = (64 queries) x (256 keys).
// 128 threads: thread pair (2q, 2q+1) shares query q; half = tid&1.
// Dim split is float4-column interleaved: half h owns cols {2d+h},
// so even/odd lanes' smem addresses differ by 16B -> conflict-free
// broadcast LDS. Partial dot products combined via shfl.xor(1).
// Bounded cosine scores -> p = exp(s) directly, no max tracking.
// Row pitch 17 float4 (272B) avoids cross-row bank conflicts.
// ============================================================
#define PITCHB 272   // 17 * 16 bytes
__global__ __launch_bounds__(128, 4) void attn_part_kernel()
{
    __shared__ float4 Ks[64*17];
    __shared__ float4 Vs[64*17];

    const int tid  = threadIdx.x;
    const int half = tid & 1;
    const int q    = tid >> 1;                 // 0..63 within tile
    const int b    = blockIdx.y;
    const int split= blockIdx.z;
    const int row  = blockIdx.x * TQ + q;      // query row within batch
    const long grow = (long)b * S + row;       // global row

    // Load this thread's half of q: float4 cols {2d+half}, d=0..7
    u64 qh[16];
    {
        const float4* qrow = (const float4*)(g_q + grow * DH);
        #pragma unroll
        for (int d = 0; d < 8; d++) {
            float4 f = qrow[2*d + half];
            qh[2*d]   = pack2(f.x, f.y);
            qh[2*d+1] = pack2(f.z, f.w);
        }
    }
    u64 oh[16];
    #pragma unroll
    for (int i = 0; i < 16; i++) oh[i] = 0ull;
    float l = 0.f;

    const int kstart = split * KEYS_PER_SPLIT;
    const float4* Kg = (const float4*)(g_k + ((long)b * S + kstart) * DH);
    const float4* Vg = (const float4*)(g_v + ((long)b * S + kstart) * DH);
    const uint32_t ks_addr = (uint32_t)__cvta_generic_to_shared(Ks);
    const uint32_t vs_addr = (uint32_t)__cvta_generic_to_shared(Vs);
    const uint32_t hoff = (uint32_t)half * 16;  // byte offset of this half's first col

    for (int kt = 0; kt < KEYS_PER_SPLIT; kt += KTILE) {
        __syncthreads();
        // 64 rows x 16 f4, coalesced: 16 consecutive threads load one row
        #pragma unroll
        for (int i = 0; i < 8; i++) {
            int idx = tid + i*128;
            int r = idx >> 4, c = idx & 15;
            Ks[r*17 + c] = Kg[(kt + r)*16 + c];
            Vs[r*17 + c] = Vg[(kt + r)*16 + c];
        }
        __syncthreads();

        #pragma unroll 2
        for (int j = 0; j < KTILE; j++) {
            const uint32_t krow = ks_addr + (uint32_t)j * PITCHB + hoff;
            u64 a0 = 0ull, a1 = 0ull, a2 = 0ull, a3 = 0ull;
            #pragma unroll
            for (int d = 0; d < 8; d += 2) {
                u64 ka, kb, kc, kd;
                lds_f4_u64(ka, kb, krow + d*32);
                lds_f4_u64(kc, kd, krow + d*32 + 32);
                fma2(a0, qh[2*d],   ka);
                fma2(a1, qh[2*d+1], kb);
                fma2(a2, qh[2*d+2], kc);
                fma2(a3, qh[2*d+3], kd);
            }
            float2 sf = unpack2(add2(add2(a0, a1), add2(a2, a3)));
            float s_part = sf.x + sf.y;
            float s = s_part + __shfl_xor_sync(0xffffffffu, s_part, 1, 32);
            float p = __expf(s);
            l += p;
            u64 p2 = pack2(p, p);

            const uint32_t vrow = vs_addr + (uint32_t)j * PITCHB + hoff;
            #pragma unroll
            for (int d = 0; d < 8; d++) {
                u64 va, vb;
                lds_f4_u64(va, vb, vrow + d*32);
                fma2(oh[2*d],   p2, va);
                fma2(oh[2*d+1], p2, vb);
            }
        }
    }

    // Write partials (unnormalized)
    float4* orow = (float4*)(g_opart + ((size_t)split * NROWS + grow) * DH);
    #pragma unroll
    for (int d = 0; d < 8; d++) {
        float2 f0 = unpack2(oh[2*d]);
        float2 f1 = unpack2(oh[2*d+1]);
        float4 o; o.x = f0.x; o.y = f0.y; o.z = f1.x; o.w = f1.y;
        orow[2*d + half] = o;
    }
    if (half == 0) g_lpart[(size_t)split * NROWS + grow] = l;
}

// ============================================================
// Attention pass 2: combine splits. One thread per float4 of output.
// ============================================================
__global__ __launch_bounds__(256) void attn_combine_kernel(float* __restrict__ out)
{
    const int id  = blockIdx.x * 256 + threadIdx.x;   // 0 .. NROWS*16-1
    const int row = id >> 4;
    const int c   = id & 15;

    float4 acc = make_float4(0.f, 0.f, 0.f, 0.f);
    float L = 0.f;
    #pragma unroll
    for (int s = 0; s < KSPLIT; s++) {
        const float4 v = ((const float4*)(g_opart + ((size_t)s * NROWS + row) * DH))[c];
        acc.x += v.x; acc.y += v.y; acc.z += v.z; acc.w += v.w;
        L += g_lpart[(size_t)s * NROWS + row];
    }
    const float inv = 1.0f / L;
    float4 o; o.x = acc.x*inv; o.y = acc.y*inv; o.z = acc.z*inv; o.w = acc.w*inv;
    ((float4*)out)[id] = o;
}

// ============================================================
extern "C" void kernel_launch(void* const* d_in, const int* in_sizes, int n_in,
                              void* d_out, int out_size)
{
    const float* query = (const float*)d_in[0];
    const float* key   = (const float*)d_in[1];
    const float* value = (const float*)d_in[2];
    const float* Wq    = (const float*)d_in[3];
    const float* bq    = (const float*)d_in[4];
    const float* Wk    = (const float*)d_in[5];
    const float* bk    = (const float*)d_in[6];
    const float* Wv    = (const float*)d_in[7];
    const float* bv    = (const float*)d_in[8];
    float* out = (float*)d_out;

    dim3 pgrid(NROWS / 128, 3);
    proj_kernel<<<pgrid, 128>>>(query, key, value, Wq, bq, Wk, bk, Wv, bv);

    dim3 agrid(S / TQ, B, KSPLIT);     // 32 x 8 x 8 = 2048 CTAs
    attn_part_kernel<<<agrid, 128>>>();

    attn_combine_kernel<<<NROWS * 16 / 256, 256>>>(out);
}

// round 3
// speedup vs baseline: 1.1830x; 1.0395x over previous
#include <cuda_runtime.h>
#include <cstdint>

// Problem constants
#define B 8
#define S 2048
#define DIN 768
#define DH 64
#define NROWS (B*S)      // 16384
#define KSPLIT 4
#define KEYS_PER_SPLIT (S/KSPLIT)   // 512
#define KTILE 64
#define QTILE 64

// Projected tensors. qT/kT are TRANSPOSED: [b][d][s] (normalized; q pre-scaled 0.125)
__device__ float g_qT[B*DH*S];
__device__ float g_kT[B*DH*S];
__device__ float g_v[NROWS*DH];
// Split-K partials
__device__ float g_opart[KSPLIT*NROWS*DH];   // 16 MB
__device__ float g_lpart[KSPLIT*NROWS];

typedef unsigned long long u64;

// ---- packed f32x2 helpers (sm_103a) ----
__device__ __forceinline__ void fma2(u64 &d, u64 a, u64 b) {
    asm("fma.rn.f32x2 %0, %1, %2, %0;" : "+l"(d) : "l"(a), "l"(b));
}
__device__ __forceinline__ u64 add2(u64 a, u64 b) {
    u64 r; asm("add.rn.f32x2 %0, %1, %2;" : "=l"(r) : "l"(a), "l"(b)); return r;
}
__device__ __forceinline__ u64 pack2(float lo, float hi) {
    u64 r; asm("mov.b64 %0, {%1, %2};" : "=l"(r) : "f"(lo), "f"(hi)); return r;
}
__device__ __forceinline__ float2 unpack2(u64 v) {
    float2 f; asm("mov.b64 {%0, %1}, %2;" : "=f"(f.x), "=f"(f.y) : "l"(v)); return f;
}
__device__ __forceinline__ void lds64(u64 &a, uint32_t addr) {
    asm volatile("ld.shared.b64 %0, [%1];" : "=l"(a) : "r"(addr));
}
__device__ __forceinline__ void lds128_u64x2(u64 &a, u64 &b, uint32_t addr) {
    asm volatile("ld.shared.v2.u64 {%0, %1}, [%2];" : "=l"(a), "=l"(b) : "r"(addr));
}
__device__ __forceinline__ float4 lds_f4(uint32_t addr) {
    float4 f;
    asm volatile("ld.shared.v4.f32 {%0, %1, %2, %3}, [%4];"
                 : "=f"(f.x), "=f"(f.y), "=f"(f.z), "=f"(f.w) : "r"(addr));
    return f;
}
__device__ __forceinline__ void sts64(uint32_t addr, u64 v) {
    asm volatile("st.shared.b64 [%0], %1;" :: "r"(addr), "l"(v));
}

// ============================================================
// Projection v2: register-tiled GEMM. CTA = 128 rows x 64 cols, 128 threads,
// thread (tr = t>>3, tc = t&7) owns 8 rows x 8 cols (32 f32x2 accs, lo/hi = row pair).
// X transposed into smem k-major (pitch 130 -> conflict-light), W chunked k=32.
// Epilogue: which 0 (q): /||row|| * 0.125, write g_qT transposed
//           which 1 (k): /||row||,        write g_kT transposed
//           which 2 (v): raw,             write g_v row-major
// ============================================================
#define KC 32
#define XPITCH 130
__global__ __launch_bounds__(128) void proj_kernel(
    const float* __restrict__ Xq, const float* __restrict__ Xk, const float* __restrict__ Xv,
    const float* __restrict__ Wq, const float* __restrict__ bq,
    const float* __restrict__ Wk, const float* __restrict__ bk,
    const float* __restrict__ Wv, const float* __restrict__ bv)
{
    __shared__ float Xs[KC * XPITCH];   // 16.6 KB, [k][row]
    __shared__ float Ws[KC * DH];       // 8 KB,   [k][col]

    const int which = blockIdx.y;
    const float* X; const float* W; const float* bias;
    if (which == 0)      { X = Xq; W = Wq; bias = bq; }
    else if (which == 1) { X = Xk; W = Wk; bias = bk; }
    else                 { X = Xv; W = Wv; bias = bv; }

    const int tid = threadIdx.x;
    const int tr = tid >> 3;   // 0..15, rows tr*8..+7
    const int tc = tid & 7;    // 0..7,  cols tc*8..+7
    const int rowblock = blockIdx.x * 128;

    // acc[rr][c]: lo = C[2rr][c], hi = C[2rr+1][c], col = tc*8+c
    u64 acc[4][8];
    #pragma unroll
    for (int c = 0; c < 8; c++) {
        float bc = bias[tc*8 + c];
        u64 bb = pack2(bc, bc);
        #pragma unroll
        for (int rr = 0; rr < 4; rr++) acc[rr][c] = bb;
    }

    const uint32_t xs = (uint32_t)__cvta_generic_to_shared(Xs);
    const uint32_t ws = (uint32_t)__cvta_generic_to_shared(Ws);

    for (int k0 = 0; k0 < DIN; k0 += KC) {
        __syncthreads();
        // X chunk: 128 rows x 32 k, load f4 along k (quarter-warp 128B coalesced),
        // store transposed scalar (2-way max conflicts with pitch 130)
        #pragma unroll
        for (int i = 0; i < 8; i++) {
            int fidx = tid + i*128;
            int row = fidx >> 3, c4 = fidx & 7;
            float4 x = *(const float4*)(X + (size_t)(rowblock + row)*DIN + k0 + c4*4);
            Xs[(4*c4+0)*XPITCH + row] = x.x;
            Xs[(4*c4+1)*XPITCH + row] = x.y;
            Xs[(4*c4+2)*XPITCH + row] = x.z;
            Xs[(4*c4+3)*XPITCH + row] = x.w;
        }
        // W chunk: straight copy 32x64
        #pragma unroll
        for (int i = 0; i < 4; i++) {
            int fidx = tid + i*128;
            int kk = fidx >> 4, c4 = fidx & 15;
            *(float4*)&Ws[kk*DH + c4*4] = *(const float4*)(W + (size_t)(k0+kk)*DH + c4*4);
        }
        __syncthreads();

        #pragma unroll 4
        for (int kk = 0; kk < KC; kk++) {
            u64 a[4];
            uint32_t xrow = xs + (uint32_t)(kk*XPITCH + tr*8)*4;
            lds64(a[0], xrow);
            lds64(a[1], xrow + 8);
            lds64(a[2], xrow + 16);
            lds64(a[3], xrow + 24);
            float4 b0 = lds_f4(ws + (uint32_t)(kk*DH + tc*8)*4);
            float4 b1 = lds_f4(ws + (uint32_t)(kk*DH + tc*8)*4 + 16);
            u64 bd[8];
            bd[0] = pack2(b0.x, b0.x); bd[1] = pack2(b0.y, b0.y);
            bd[2] = pack2(b0.z, b0.z); bd[3] = pack2(b0.w, b0.w);
            bd[4] = pack2(b1.x, b1.x); bd[5] = pack2(b1.y, b1.y);
            bd[6] = pack2(b1.z, b1.z); bd[7] = pack2(b1.w, b1.w);
            #pragma unroll
            for (int rr = 0; rr < 4; rr++)
                #pragma unroll
                for (int c = 0; c < 8; c++)
                    fma2(acc[rr][c], a[rr], bd[c]);
        }
    }

    // epilogue
    float res[8][8];
    #pragma unroll
    for (int rr = 0; rr < 4; rr++)
        #pragma unroll
        for (int c = 0; c < 8; c++) {
            float2 f = unpack2(acc[rr][c]);
            res[2*rr][c] = f.x; res[2*rr+1][c] = f.y;
        }

    if (which < 2) {
        // row norms: partial over this thread's 8 cols, reduce across tc lanes (bits 0-2)
        #pragma unroll
        for (int r = 0; r < 8; r++) {
            float ss = 0.f;
            #pragma unroll
            for (int c = 0; c < 8; c++) ss += res[r][c]*res[r][c];
            ss += __shfl_xor_sync(0xffffffffu, ss, 1);
            ss += __shfl_xor_sync(0xffffffffu, ss, 2);
            ss += __shfl_xor_sync(0xffffffffu, ss, 4);
            float sc = rsqrtf(ss);
            if (which == 0) sc *= 0.125f;
            #pragma unroll
            for (int c = 0; c < 8; c++) res[r][c] *= sc;
        }
        // transposed scatter: out[b][d][q]
        const int bb = rowblock >> 11;
        const int qb = (rowblock & (S-1)) + tr*8;
        float* out = (which == 0 ? g_qT : g_kT) + (size_t)bb * DH * S;
        #pragma unroll
        for (int c = 0; c < 8; c++) {
            float* col = out + (size_t)(tc*8 + c) * S + qb;
            #pragma unroll
            for (int r = 0; r < 8; r++) col[r] = res[r][c];
        }
    } else {
        #pragma unroll
        for (int r = 0; r < 8; r++) {
            float* orow = g_v + (size_t)(rowblock + tr*8 + r) * DH + tc*8;
            float4 v0 = make_float4(res[r][0], res[r][1], res[r][2], res[r][3]);
            float4 v1 = make_float4(res[r][4], res[r][5], res[r][6], res[r][7]);
            *(float4*)orow = v0;
            *(float4*)(orow + 4) = v1;
        }
    }
}

// ============================================================
// Attention pass 1 (split-K, register-tiled):
// CTA = 64 queries x 512 keys (8 tiles of 64), 128 threads.
// Per key tile:
//   stage A: S = Q.K^T outer-product over d (thread: 8q x 4k, lo/hi = q-pair)
//            exp in regs (bounded cosine scores), accumulate l, store P to smem
//   stage B: O += P.V outer-product over keys (thread: 8q x 4d)
// All smem tiles pitch 68 floats -> aligned f4, conflict-free loads.
// ============================================================
#define PITCH 68
__global__ __launch_bounds__(128) void attn_part_kernel()
{
    extern __shared__ float sm[];
    float* Qs = sm;                 // [d][q]   64x68
    float* Ks = sm + 64*PITCH;      // [d][key]
    float* Vs = sm + 2*64*PITCH;    // [key][d]
    float* Ps = sm + 3*64*PITCH;    // [key][q]

    const int tid = threadIdx.x;
    const int tq = tid & 7;     // q-frag base = 8*tq
    const int tk = tid >> 3;    // 0..15: stage A keys 4*tk..+3; stage B dims 4*tk..+3
    const int b = blockIdx.y;
    const int split = blockIdx.z;
    const int q0 = blockIdx.x * QTILE;
    const int key0 = split * KEYS_PER_SPLIT;

    const uint32_t qs = (uint32_t)__cvta_generic_to_shared(Qs);
    const uint32_t ks = (uint32_t)__cvta_generic_to_shared(Ks);
    const uint32_t vs = (uint32_t)__cvta_generic_to_shared(Vs);
    const uint32_t ps = (uint32_t)__cvta_generic_to_shared(Ps);

    // Load Q tile [64 d][64 q] from g_qT (coalesced 256B bursts per d-row)
    {
        const float* src = g_qT + (size_t)b * DH * S + q0;
        #pragma unroll
        for (int i = 0; i < 8; i++) {
            int fidx = tid + i*128;
            int d = fidx >> 4, c4 = fidx & 15;
            *(float4*)&Qs[d*PITCH + c4*4] = *(const float4*)(src + (size_t)d*S + c4*4);
        }
    }

    u64 o2[4][4];   // [q-pair rr][d c]
    u64 l2[4];      // l sums, q-pairs
    #pragma unroll
    for (int rr = 0; rr < 4; rr++) {
        l2[rr] = 0ull;
        #pragma unroll
        for (int c = 0; c < 4; c++) o2[rr][c] = 0ull;
    }

    for (int kt = 0; kt < KEYS_PER_SPLIT; kt += KTILE) {
        __syncthreads();
        const float* ksrc = g_kT + (size_t)b * DH * S + key0 + kt;
        const float* vsrc = g_v + ((size_t)b * S + key0 + kt) * DH;
        #pragma unroll
        for (int i = 0; i < 8; i++) {
            int fidx = tid + i*128;
            int r = fidx >> 4, c4 = fidx & 15;
            *(float4*)&Ks[r*PITCH + c4*4] = *(const float4*)(ksrc + (size_t)r*S + c4*4);
            *(float4*)&Vs[r*PITCH + c4*4] = *(const float4*)(vsrc + (size_t)r*DH + c4*4);
        }
        __syncthreads();

        // ---- stage A: scores ----
        u64 s2[4][4];
        #pragma unroll
        for (int rr = 0; rr < 4; rr++)
            #pragma unroll
            for (int j = 0; j < 4; j++) s2[rr][j] = 0ull;

        #pragma unroll 4
        for (int d = 0; d < 64; d++) {
            u64 qa[4];
            uint32_t qaddr = qs + (uint32_t)(d*PITCH + tq*8)*4;
            lds128_u64x2(qa[0], qa[1], qaddr);
            lds128_u64x2(qa[2], qa[3], qaddr + 16);
            float4 kf = lds_f4(ks + (uint32_t)(d*PITCH + tk*4)*4);
            u64 kd[4];
            kd[0] = pack2(kf.x, kf.x); kd[1] = pack2(kf.y, kf.y);
            kd[2] = pack2(kf.z, kf.z); kd[3] = pack2(kf.w, kf.w);
            #pragma unroll
            for (int rr = 0; rr < 4; rr++)
                #pragma unroll
                for (int j = 0; j < 4; j++)
                    fma2(s2[rr][j], qa[rr], kd[j]);
        }

        // exp (scores bounded by cosine attn: no max needed), l accumulate, store P^T
        #pragma unroll
        for (int rr = 0; rr < 4; rr++)
            #pragma unroll
            for (int j = 0; j < 4; j++) {
                float2 sf = unpack2(s2[rr][j]);
                u64 p2 = pack2(__expf(sf.x), __expf(sf.y));
                l2[rr] = add2(l2[rr], p2);
                sts64(ps + (uint32_t)((tk*4 + j)*PITCH + tq*8 + 2*rr)*4, p2);
            }
        __syncthreads();

        // ---- stage B: O += P.V ----
        #pragma unroll 4
        for (int k = 0; k < 64; k++) {
            u64 pa[4];
            uint32_t paddr = ps + (uint32_t)(k*PITCH + tq*8)*4;
            lds128_u64x2(pa[0], pa[1], paddr);
            lds128_u64x2(pa[2], pa[3], paddr + 16);
            float4 vf = lds_f4(vs + (uint32_t)(k*PITCH + tk*4)*4);
            u64 vd[4];
            vd[0] = pack2(vf.x, vf.x); vd[1] = pack2(vf.y, vf.y);
            vd[2] = pack2(vf.z, vf.z); vd[3] = pack2(vf.w, vf.w);
            #pragma unroll
            for (int rr = 0; rr < 4; rr++)
                #pragma unroll
                for (int c = 0; c < 4; c++)
                    fma2(o2[rr][c], pa[rr], vd[c]);
        }
    }

    // write O partials (unnormalized)
    float* op = g_opart + ((size_t)split * NROWS + (size_t)b * S + q0) * DH;
    #pragma unroll
    for (int rr = 0; rr < 4; rr++) {
        float2 f0 = unpack2(o2[rr][0]);
        float2 f1 = unpack2(o2[rr][1]);
        float2 f2 = unpack2(o2[rr][2]);
        float2 f3 = unpack2(o2[rr][3]);
        *(float4*)&op[(tq*8 + 2*rr    )*DH + tk*4] = make_float4(f0.x, f1.x, f2.x, f3.x);
        *(float4*)&op[(tq*8 + 2*rr + 1)*DH + tk*4] = make_float4(f0.y, f1.y, f2.y, f3.y);
    }

    // l reduction: combine across tk (lane bits 3,4 + cross-warp via smem)
    #pragma unroll
    for (int rr = 0; rr < 4; rr++) {
        u64 v = l2[rr];
        v = add2(v, __shfl_xor_sync(0xffffffffu, v, 8));
        v = add2(v, __shfl_xor_sync(0xffffffffu, v, 16));
        l2[rr] = v;
    }
    __syncthreads();          // Ps no longer needed; reuse
    float* lw = Ps;           // [4 warps][64 q]
    const int lane = tid & 31, w = tid >> 5;
    if (lane < 8) {
        #pragma unroll
        for (int rr = 0; rr < 4; rr++) {
            float2 f = unpack2(l2[rr]);
            lw[w*64 + lane*8 + 2*rr]     = f.x;
            lw[w*64 + lane*8 + 2*rr + 1] = f.y;
        }
    }
    __syncthreads();
    if (tid < 64) {
        float L = lw[tid] + lw[64 + tid] + lw[128 + tid] + lw[192 + tid];
        g_lpart[(size_t)split * NROWS + (size_t)b * S + q0 + tid] = L;
    }
}

// ============================================================
// Attention pass 2: combine splits. One thread per float4 of output.
// ============================================================
__global__ __launch_bounds__(256) void attn_combine_kernel(float* __restrict__ out)
{
    const int id  = blockIdx.x * 256 + threadIdx.x;
    const int row = id >> 4;
    const int c   = id & 15;

    float4 acc = make_float4(0.f, 0.f, 0.f, 0.f);
    float L = 0.f;
    #pragma unroll
    for (int s = 0; s < KSPLIT; s++) {
        const float4 v = ((const float4*)(g_opart + ((size_t)s * NROWS + row) * DH))[c];
        acc.x += v.x; acc.y += v.y; acc.z += v.z; acc.w += v.w;
        L += g_lpart[(size_t)s * NROWS + row];
    }
    const float inv = 1.0f / L;
    ((float4*)out)[id] = make_float4(acc.x*inv, acc.y*inv, acc.z*inv, acc.w*inv);
}

// ============================================================
extern "C" void kernel_launch(void* const* d_in, const int* in_sizes, int n_in,
                              void* d_out, int out_size)
{
    const float* query = (const float*)d_in[0];
    const float* key   = (const float*)d_in[1];
    const float* value = (const float*)d_in[2];
    const float* Wq    = (const float*)d_in[3];
    const float* bq    = (const float*)d_in[4];
    const float* Wk    = (const float*)d_in[5];
    const float* bk    = (const float*)d_in[6];
    const float* Wv    = (const float*)d_in[7];
    const float* bv    = (const float*)d_in[8];
    float* out = (float*)d_out;

    static const int attn_smem = 4 * 64 * PITCH * sizeof(float);  // 69632
    cudaFuncSetAttribute(attn_part_kernel,
                         cudaFuncAttributeMaxDynamicSharedMemorySize, attn_smem);

    dim3 pgrid(NROWS / 128, 3);
    proj_kernel<<<pgrid, 128>>>(query, key, value, Wq, bq, Wk, bk, Wv, bv);

    dim3 agrid(S / QTILE, B, KSPLIT);   // 32 x 8 x 4 = 1024 CTAs
    attn_part_kernel<<<agrid, 128, attn_smem>>>();

    attn_combine_kernel<<<NROWS * 16 / 256, 256>>>(out);
}

// round 5
// speedup vs baseline: 2.4806x; 2.0968x over previous
#include <cuda_runtime.h>
#include <cuda_bf16.h>
#include <cstdint>

// Problem constants
#define B 8
#define S 2048
#define DIN 768
#define DH 64
#define NROWS (B*S)      // 16384

// Projected tensors as bf16 hi/lo pairs (hi + lo reconstructs fp32 to ~2^-18)
__device__ __nv_bfloat16 g_qh[NROWS*DH], g_ql[NROWS*DH];   // [b*S+s][d] (q normalized, pre-scaled 0.125)
__device__ __nv_bfloat16 g_kh[NROWS*DH], g_kl[NROWS*DH];   // [b*S+s][d] (normalized)
__device__ __nv_bfloat16 g_vh[B*DH*S],  g_vl[B*DH*S];      // TRANSPOSED [b][d][s]

typedef unsigned long long u64;

// ---- packed f32x2 helpers (SIMT proj) ----
__device__ __forceinline__ void fma2(u64 &d, u64 a, u64 b) {
    asm("fma.rn.f32x2 %0, %1, %2, %0;" : "+l"(d) : "l"(a), "l"(b));
}
__device__ __forceinline__ u64 pack2(float lo, float hi) {
    u64 r; asm("mov.b64 %0, {%1, %2};" : "=l"(r) : "f"(lo), "f"(hi)); return r;
}
__device__ __forceinline__ float2 unpack2(u64 v) {
    float2 f; asm("mov.b64 {%0, %1}, %2;" : "=f"(f.x), "=f"(f.y) : "l"(v)); return f;
}
__device__ __forceinline__ void lds64(u64 &a, uint32_t addr) {
    asm volatile("ld.shared.b64 %0, [%1];" : "=l"(a) : "r"(addr));
}
__device__ __forceinline__ float4 lds_f4(uint32_t addr) {
    float4 f;
    asm volatile("ld.shared.v4.f32 {%0, %1, %2, %3}, [%4];"
                 : "=f"(f.x), "=f"(f.y), "=f"(f.z), "=f"(f.w) : "r"(addr));
    return f;
}
__device__ __forceinline__ uint32_t smem_u32(const void* p) {
    uint32_t a;
    asm("{ .reg .u64 t; cvta.to.shared.u64 t, %1; cvt.u32.u64 %0, t; }" : "=r"(a) : "l"(p));
    return a;
}

// ---- base-PTX tensor core ops (sm_80+, no 'a' target needed) ----
__device__ __forceinline__ void ldsm_x4(uint32_t &r0, uint32_t &r1, uint32_t &r2, uint32_t &r3,
                                        uint32_t addr) {
    asm volatile("ldmatrix.sync.aligned.m8n8.x4.shared.b16 {%0,%1,%2,%3}, [%4];"
                 : "=r"(r0), "=r"(r1), "=r"(r2), "=r"(r3) : "r"(addr));
}
__device__ __forceinline__ void mma16816(float* c, const uint32_t* a, uint32_t b0, uint32_t b1) {
    asm volatile("mma.sync.aligned.m16n8k16.row.col.f32.bf16.bf16.f32 "
                 "{%0,%1,%2,%3}, {%4,%5,%6,%7}, {%8,%9}, {%0,%1,%2,%3};"
                 : "+f"(c[0]), "+f"(c[1]), "+f"(c[2]), "+f"(c[3])
                 : "r"(a[0]), "r"(a[1]), "r"(a[2]), "r"(a[3]), "r"(b0), "r"(b1));
}
__device__ __forceinline__ uint32_t bf2_pack(float a, float b) {
    __nv_bfloat162 h = __halves2bfloat162(__float2bfloat16(a), __float2bfloat16(b));
    return *(uint32_t*)&h;
}

// ============================================================
// Projection (SIMT fp32, register-tiled), epilogue emits bf16 hi/lo.
// which 0 (q): /||row|| * 0.125;  1 (k): /||row||;  2 (v): raw, transposed [b][d][s]
// ============================================================
#define KC 32
#define XPITCH 130
__global__ __launch_bounds__(128) void proj_kernel(
    const float* __restrict__ Xq, const float* __restrict__ Xk, const float* __restrict__ Xv,
    const float* __restrict__ Wq, const float* __restrict__ bq,
    const float* __restrict__ Wk, const float* __restrict__ bk,
    const float* __restrict__ Wv, const float* __restrict__ bv)
{
    __shared__ float Xs[KC * XPITCH];
    __shared__ float Ws[KC * DH];

    const int which = blockIdx.y;
    const float* X; const float* W; const float* bias;
    if (which == 0)      { X = Xq; W = Wq; bias = bq; }
    else if (which == 1) { X = Xk; W = Wk; bias = bk; }
    else                 { X = Xv; W = Wv; bias = bv; }

    const int tid = threadIdx.x;
    const int tr = tid >> 3;
    const int tc = tid & 7;
    const int rowblock = blockIdx.x * 128;

    u64 acc[4][8];
    #pragma unroll
    for (int c = 0; c < 8; c++) {
        float bc = bias[tc*8 + c];
        u64 bb = pack2(bc, bc);
        #pragma unroll
        for (int rr = 0; rr < 4; rr++) acc[rr][c] = bb;
    }

    const uint32_t xs = smem_u32(Xs);
    const uint32_t ws = smem_u32(Ws);

    for (int k0 = 0; k0 < DIN; k0 += KC) {
        __syncthreads();
        #pragma unroll
        for (int i = 0; i < 8; i++) {
            int fidx = tid + i*128;
            int row = fidx >> 3, c4 = fidx & 7;
            float4 x = *(const float4*)(X + (size_t)(rowblock + row)*DIN + k0 + c4*4);
            Xs[(4*c4+0)*XPITCH + row] = x.x;
            Xs[(4*c4+1)*XPITCH + row] = x.y;
            Xs[(4*c4+2)*XPITCH + row] = x.z;
            Xs[(4*c4+3)*XPITCH + row] = x.w;
        }
        #pragma unroll
        for (int i = 0; i < 4; i++) {
            int fidx = tid + i*128;
            int kk = fidx >> 4, c4 = fidx & 15;
            *(float4*)&Ws[kk*DH + c4*4] = *(const float4*)(W + (size_t)(k0+kk)*DH + c4*4);
        }
        __syncthreads();

        #pragma unroll 4
        for (int kk = 0; kk < KC; kk++) {
            u64 a[4];
            uint32_t xrow = xs + (uint32_t)(kk*XPITCH + tr*8)*4;
            lds64(a[0], xrow);
            lds64(a[1], xrow + 8);
            lds64(a[2], xrow + 16);
            lds64(a[3], xrow + 24);
            float4 b0 = lds_f4(ws + (uint32_t)(kk*DH + tc*8)*4);
            float4 b1 = lds_f4(ws + (uint32_t)(kk*DH + tc*8)*4 + 16);
            u64 bd[8];
            bd[0] = pack2(b0.x, b0.x); bd[1] = pack2(b0.y, b0.y);
            bd[2] = pack2(b0.z, b0.z); bd[3] = pack2(b0.w, b0.w);
            bd[4] = pack2(b1.x, b1.x); bd[5] = pack2(b1.y, b1.y);
            bd[6] = pack2(b1.z, b1.z); bd[7] = pack2(b1.w, b1.w);
            #pragma unroll
            for (int rr = 0; rr < 4; rr++)
                #pragma unroll
                for (int c = 0; c < 8; c++)
                    fma2(acc[rr][c], a[rr], bd[c]);
        }
    }

    float res[8][8];
    #pragma unroll
    for (int rr = 0; rr < 4; rr++)
        #pragma unroll
        for (int c = 0; c < 8; c++) {
            float2 f = unpack2(acc[rr][c]);
            res[2*rr][c] = f.x; res[2*rr+1][c] = f.y;
        }

    if (which < 2) {
        #pragma unroll
        for (int r = 0; r < 8; r++) {
            float ss = 0.f;
            #pragma unroll
            for (int c = 0; c < 8; c++) ss += res[r][c]*res[r][c];
            ss += __shfl_xor_sync(0xffffffffu, ss, 1);
            ss += __shfl_xor_sync(0xffffffffu, ss, 2);
            ss += __shfl_xor_sync(0xffffffffu, ss, 4);
            float sc = rsqrtf(ss);
            if (which == 0) sc *= 0.125f;
            #pragma unroll
            for (int c = 0; c < 8; c++) res[r][c] *= sc;
        }
        __nv_bfloat16* gh = (which == 0) ? g_qh : g_kh;
        __nv_bfloat16* gl = (which == 0) ? g_ql : g_kl;
        #pragma unroll
        for (int r = 0; r < 8; r++) {
            __nv_bfloat16 h[8], lo[8];
            #pragma unroll
            for (int c = 0; c < 8; c++) {
                h[c]  = __float2bfloat16(res[r][c]);
                lo[c] = __float2bfloat16(res[r][c] - __bfloat162float(h[c]));
            }
            size_t base = (size_t)(rowblock + tr*8 + r)*DH + tc*8;
            *(uint4*)&gh[base] = *(uint4*)h;
            *(uint4*)&gl[base] = *(uint4*)lo;
        }
    } else {
        const int bb = rowblock >> 11;
        const int s0 = (rowblock & (S-1)) + tr*8;
        #pragma unroll
        for (int c = 0; c < 8; c++) {
            __nv_bfloat16 h[8], lo[8];
            #pragma unroll
            for (int r = 0; r < 8; r++) {
                h[r]  = __float2bfloat16(res[r][c]);
                lo[r] = __float2bfloat16(res[r][c] - __bfloat162float(h[r]));
            }
            size_t base = ((size_t)bb*DH + tc*8 + c)*S + s0;
            *(uint4*)&g_vh[base] = *(uint4*)h;
            *(uint4*)&g_vl[base] = *(uint4*)lo;
        }
    }
}

// ============================================================
// mma.sync flash attention (bf16x3 ~ fp32 accuracy):
// CTA = 128 queries (8 warps x m16), 256 threads. Keys streamed in 64-tiles.
// S-frags = Q.K^T via m16n8k16 (hi*hi + hi*lo + lo*hi); p = exp(s) (bounded
// cosine scores, no max); P accumulator frags repacked in-register as A-frags
// (FA2 trick); O += P.V from V^T smem. Epilogue: O / l.
// smem rows pitch 72 halves (144B) -> conflict-free LDSM/store phases.
// ============================================================
#define TPITCH 72
__global__ __launch_bounds__(256) void attn_kernel(float* __restrict__ out)
{
    __shared__ __nv_bfloat16 TS[4 * 64 * TPITCH];   // 36864 B

    const int tid = threadIdx.x;
    const int warp = tid >> 5;
    const int lane = tid & 31;
    const int b = blockIdx.y;
    const int q0 = blockIdx.x * 128;

    const int R = 64 * TPITCH;   // 4608 halves per region
    __nv_bfloat16* Kh = TS;
    __nv_bfloat16* Kl = TS + R;
    __nv_bfloat16* Vh = TS + 2*R;
    __nv_bfloat16* Vl = TS + 3*R;

    // ---- Q phase: stage in smem (Qh at 0, Ql at 2R), load A-frags ----
    {
        const uint4* qh_g = (const uint4*)(g_qh + ((size_t)b*S + q0)*DH);
        const uint4* ql_g = (const uint4*)(g_ql + ((size_t)b*S + q0)*DH);
        #pragma unroll
        for (int i = 0; i < 4; i++) {
            int idx = tid + i*256;          // 0..1023 (128 rows x 8 uint4)
            int r = idx >> 3, c = idx & 7;
            *(uint4*)&TS[r*TPITCH + c*8]       = qh_g[idx];
            *(uint4*)&TS[2*R + r*TPITCH + c*8] = ql_g[idx];
        }
    }
    __syncthreads();

    uint32_t qfh[4][4], qfl[4][4];
    {
        const int arow = warp*16 + (lane & 15);
        const int acol = (lane >> 4) * 8;
        #pragma unroll
        for (int k = 0; k < 4; k++) {
            ldsm_x4(qfh[k][0], qfh[k][1], qfh[k][2], qfh[k][3],
                    smem_u32(&TS[arow*TPITCH + k*16 + acol]));
            ldsm_x4(qfl[k][0], qfl[k][1], qfl[k][2], qfl[k][3],
                    smem_u32(&TS[2*R + arow*TPITCH + k*16 + acol]));
        }
    }

    float oacc[8][4];
    #pragma unroll
    for (int j = 0; j < 8; j++)
        #pragma unroll
        for (int i = 0; i < 4; i++) oacc[j][i] = 0.f;
    float lsum0 = 0.f, lsum1 = 0.f;

    // B-frag ldmatrix lane pattern (two n-tiles per x4)
    const int brow = (lane & 7) | ((lane & 16) >> 1);
    const int bcol = (lane & 8);

    const uint4* kh_g = (const uint4*)(g_kh + (size_t)b*S*DH);
    const uint4* kl_g = (const uint4*)(g_kl + (size_t)b*S*DH);
    const __nv_bfloat16* vh_g = g_vh + (size_t)b*DH*S;
    const __nv_bfloat16* vl_g = g_vl + (size_t)b*DH*S;

    for (int kt = 0; kt < S/64; kt++) {
        const int key0 = kt * 64;
        __syncthreads();
        // K tile [64 keys][64 d], V^T tile [64 d][64 keys], hi+lo
        #pragma unroll
        for (int i = 0; i < 2; i++) {
            int idx = tid + i*256;          // 0..511
            int r = idx >> 3, c = idx & 7;
            *(uint4*)&Kh[r*TPITCH + c*8] = kh_g[(size_t)(key0 + r)*8 + c];
            *(uint4*)&Kl[r*TPITCH + c*8] = kl_g[(size_t)(key0 + r)*8 + c];
            *(uint4*)&Vh[r*TPITCH + c*8] = *(const uint4*)(vh_g + (size_t)r*S + key0 + c*8);
            *(uint4*)&Vl[r*TPITCH + c*8] = *(const uint4*)(vl_g + (size_t)r*S + key0 + c*8);
        }
        __syncthreads();

        // ---- S = Q.K^T ----
        float sacc[8][4];
        #pragma unroll
        for (int j = 0; j < 8; j++)
            #pragma unroll
            for (int i = 0; i < 4; i++) sacc[j][i] = 0.f;

        #pragma unroll
        for (int k = 0; k < 4; k++) {
            #pragma unroll
            for (int jj = 0; jj < 8; jj += 2) {
                uint32_t bh0,bh1,bh2,bh3, bl0,bl1,bl2,bl3;
                ldsm_x4(bh0,bh1,bh2,bh3, smem_u32(&Kh[(jj*8 + brow)*TPITCH + k*16 + bcol]));
                ldsm_x4(bl0,bl1,bl2,bl3, smem_u32(&Kl[(jj*8 + brow)*TPITCH + k*16 + bcol]));
                mma16816(sacc[jj],   qfh[k], bh0, bh1);
                mma16816(sacc[jj],   qfh[k], bl0, bl1);
                mma16816(sacc[jj],   qfl[k], bh0, bh1);
                mma16816(sacc[jj+1], qfh[k], bh2, bh3);
                mma16816(sacc[jj+1], qfh[k], bl2, bl3);
                mma16816(sacc[jj+1], qfl[k], bh2, bh3);
            }
        }

        // ---- p = exp(s); repack accumulators as A-frags (hi/lo) ----
        uint32_t pfh[4][4], pfl[4][4];
        #pragma unroll
        for (int j = 0; j < 8; j++) {
            float p0 = __expf(sacc[j][0]);
            float p1 = __expf(sacc[j][1]);
            float p2 = __expf(sacc[j][2]);
            float p3 = __expf(sacc[j][3]);
            lsum0 += p0 + p1;
            lsum1 += p2 + p3;
            float h0 = __bfloat162float(__float2bfloat16(p0));
            float h1 = __bfloat162float(__float2bfloat16(p1));
            float h2 = __bfloat162float(__float2bfloat16(p2));
            float h3 = __bfloat162float(__float2bfloat16(p3));
            int kk = j >> 1, o = (j & 1) * 2;
            pfh[kk][o]   = bf2_pack(h0, h1);
            pfh[kk][o+1] = bf2_pack(h2, h3);
            pfl[kk][o]   = bf2_pack(p0 - h0, p1 - h1);
            pfl[kk][o+1] = bf2_pack(p2 - h2, p3 - h3);
        }

        // ---- O += P.V ----
        #pragma unroll
        for (int kk = 0; kk < 4; kk++) {
            #pragma unroll
            for (int jj = 0; jj < 8; jj += 2) {
                uint32_t vh0,vh1,vh2,vh3, vl0,vl1,vl2,vl3;
                ldsm_x4(vh0,vh1,vh2,vh3, smem_u32(&Vh[(jj*8 + brow)*TPITCH + kk*16 + bcol]));
                ldsm_x4(vl0,vl1,vl2,vl3, smem_u32(&Vl[(jj*8 + brow)*TPITCH + kk*16 + bcol]));
                mma16816(oacc[jj],   pfh[kk], vh0, vh1);
                mma16816(oacc[jj],   pfh[kk], vl0, vl1);
                mma16816(oacc[jj],   pfl[kk], vh0, vh1);
                mma16816(oacc[jj+1], pfh[kk], vh2, vh3);
                mma16816(oacc[jj+1], pfh[kk], vl2, vl3);
                mma16816(oacc[jj+1], pfl[kk], vh2, vh3);
            }
        }
    }

    // ---- epilogue: row sums, normalize, store ----
    lsum0 += __shfl_xor_sync(0xffffffffu, lsum0, 1);
    lsum0 += __shfl_xor_sync(0xffffffffu, lsum0, 2);
    lsum1 += __shfl_xor_sync(0xffffffffu, lsum1, 1);
    lsum1 += __shfl_xor_sync(0xffffffffu, lsum1, 2);
    const float inv0 = 1.0f / lsum0;
    const float inv1 = 1.0f / lsum1;

    const int r0 = q0 + warp*16 + (lane >> 2);
    const int cc = (lane & 3) * 2;
    float* o0 = out + ((size_t)b*S + r0)*DH + cc;
    float* o1 = o0 + 8*DH;
    #pragma unroll
    for (int j = 0; j < 8; j++) {
        *(float2*)(o0 + j*8) = make_float2(oacc[j][0]*inv0, oacc[j][1]*inv0);
        *(float2*)(o1 + j*8) = make_float2(oacc[j][2]*inv1, oacc[j][3]*inv1);
    }
}

// ============================================================
extern "C" void kernel_launch(void* const* d_in, const int* in_sizes, int n_in,
                              void* d_out, int out_size)
{
    const float* query = (const float*)d_in[0];
    const float* key   = (const float*)d_in[1];
    const float* value = (const float*)d_in[2];
    const float* Wq    = (const float*)d_in[3];
    const float* bq    = (const float*)d_in[4];
    const float* Wk    = (const float*)d_in[5];
    const float* bk    = (const float*)d_in[6];
    const float* Wv    = (const float*)d_in[7];
    const float* bv    = (const float*)d_in[8];
    float* out = (float*)d_out;

    dim3 pgrid(NROWS / 128, 3);
    proj_kernel<<<pgrid, 128>>>(query, key, value, Wq, bq, Wk, bk, Wv, bv);

    dim3 agrid(S / 128, B);    // 16 x 8 = 128 CTAs
    attn_kernel<<<agrid, 256>>>(out);
}

// round 6
// speedup vs baseline: 2.5955x; 1.0463x over previous
#include <cuda_runtime.h>
#include <cuda_bf16.h>
#include <cstdint>

// Problem constants
#define B 8
#define S 2048
#define DIN 768
#define DH 64
#define NROWS (B*S)      // 16384

// Projected tensors as bf16 hi/lo pairs (hi + lo reconstructs fp32 to ~2^-18)
__device__ __nv_bfloat16 g_qh[NROWS*DH], g_ql[NROWS*DH];   // [b*S+s][d] (q normalized, pre-scaled 0.125)
__device__ __nv_bfloat16 g_kh[NROWS*DH], g_kl[NROWS*DH];   // [b*S+s][d] (normalized)
__device__ __nv_bfloat16 g_vh[B*DH*S],  g_vl[B*DH*S];      // TRANSPOSED [b][d][s]

__device__ __forceinline__ uint32_t smem_u32(const void* p) {
    uint32_t a;
    asm("{ .reg .u64 t; cvta.to.shared.u64 t, %1; cvt.u32.u64 %0, t; }" : "=r"(a) : "l"(p));
    return a;
}

// ---- base-PTX tensor core ops (sm_80+, compile for plain sm_103) ----
__device__ __forceinline__ void ldsm_x4(uint32_t &r0, uint32_t &r1, uint32_t &r2, uint32_t &r3,
                                        uint32_t addr) {
    asm volatile("ldmatrix.sync.aligned.m8n8.x4.shared.b16 {%0,%1,%2,%3}, [%4];"
                 : "=r"(r0), "=r"(r1), "=r"(r2), "=r"(r3) : "r"(addr));
}
__device__ __forceinline__ void mma16816(float* c, const uint32_t* a, uint32_t b0, uint32_t b1) {
    asm volatile("mma.sync.aligned.m16n8k16.row.col.f32.bf16.bf16.f32 "
                 "{%0,%1,%2,%3}, {%4,%5,%6,%7}, {%8,%9}, {%0,%1,%2,%3};"
                 : "+f"(c[0]), "+f"(c[1]), "+f"(c[2]), "+f"(c[3])
                 : "r"(a[0]), "r"(a[1]), "r"(a[2]), "r"(a[3]), "r"(b0), "r"(b1));
}
__device__ __forceinline__ uint32_t bf2_pack(float a, float b) {
    __nv_bfloat162 h = __halves2bfloat162(__float2bfloat16(a), __float2bfloat16(b));
    return *(uint32_t*)&h;
}
// split two fp32 into packed bf16x2 hi and bf16x2 lo
__device__ __forceinline__ void split2(float a, float b, uint32_t &hp, uint32_t &lp) {
    __nv_bfloat16 ha = __float2bfloat16(a), hb = __float2bfloat16(b);
    __nv_bfloat16 la = __float2bfloat16(a - __bfloat162float(ha));
    __nv_bfloat16 lb = __float2bfloat16(b - __bfloat162float(hb));
    __nv_bfloat162 hh = __halves2bfloat162(ha, hb);
    __nv_bfloat162 ll = __halves2bfloat162(la, lb);
    hp = *(uint32_t*)&hh; lp = *(uint32_t*)&ll;
}

// ============================================================
// Projection (tensor, bf16x3): CTA = 128 rows x 64 cols, 256 threads (8 warps,
// warp w = rows w*16..+15). K chunked by 64; X fp32 -> bf16 hi/lo split during
// smem staging; W chunk staged TRANSPOSED [n][k] so the attn ldsm/mma pattern
// applies unchanged. Epilogue: +bias; q/k: L2-norm (q * 0.125); v: transpose
// through smem for coalesced [b][d][s] stores. All outputs bf16 hi/lo.
// ============================================================
#define PP 72     // [row][k] tile pitch (halves): 144B rows -> conflict-free ldsm
#define TP 136    // v-transpose buffer pitch (halves): 272B, 16B-aligned rows
#define PROJ_SMEM ((2*128*PP + 2*64*PP) * 2)   // 55296 B

__global__ __launch_bounds__(256, 2) void proj_kernel(
    const float* __restrict__ Xq, const float* __restrict__ Xk, const float* __restrict__ Xv,
    const float* __restrict__ Wq, const float* __restrict__ bq,
    const float* __restrict__ Wk, const float* __restrict__ bk,
    const float* __restrict__ Wv, const float* __restrict__ bv)
{
    extern __shared__ char psm[];
    __nv_bfloat16* Xh = (__nv_bfloat16*)psm;        // 128 x PP
    __nv_bfloat16* Xl = Xh + 128*PP;
    __nv_bfloat16* Wh = Xl + 128*PP;                // 64 x PP  [n][k]
    __nv_bfloat16* Wl = Wh + 64*PP;

    const int which = blockIdx.y;
    const float* X; const float* W; const float* bias;
    if (which == 0)      { X = Xq; W = Wq; bias = bq; }
    else if (which == 1) { X = Xk; W = Wk; bias = bk; }
    else                 { X = Xv; W = Wv; bias = bv; }

    const int tid = threadIdx.x;
    const int warp = tid >> 5;
    const int lane = tid & 31;
    const int rowblock = blockIdx.x * 128;

    float cacc[8][4];
    #pragma unroll
    for (int j = 0; j < 8; j++)
        #pragma unroll
        for (int i = 0; i < 4; i++) cacc[j][i] = 0.f;

    const int arow = warp*16 + (lane & 15);
    const int acol = (lane >> 4) * 8;
    const int brow = (lane & 7) | ((lane & 16) >> 1);
    const int bcol = (lane & 8);

    for (int k0 = 0; k0 < DIN; k0 += 64) {
        __syncthreads();
        // stage X [128 rows x 64 k] fp32 -> hi/lo
        #pragma unroll
        for (int i = 0; i < 8; i++) {
            int idx = tid + i*256;          // float4 units: 128 x 16
            int r = idx >> 4, c4 = idx & 15;
            float4 x = *(const float4*)(X + (size_t)(rowblock + r)*DIN + k0 + c4*4);
            uint32_t h0, l0, h1, l1;
            split2(x.x, x.y, h0, l0);
            split2(x.z, x.w, h1, l1);
            *(uint2*)&Xh[r*PP + c4*4] = make_uint2(h0, h1);
            *(uint2*)&Xl[r*PP + c4*4] = make_uint2(l0, l1);
        }
        // stage W chunk transposed: [k 64][n 64] -> [n][k]
        #pragma unroll
        for (int i = 0; i < 4; i++) {
            int idx = tid + i*256;          // float4 units: 64 x 16
            int kk = idx >> 4, n4 = idx & 15;
            float4 w = *(const float4*)(W + (size_t)(k0 + kk)*DH + n4*4);
            float ws4[4] = {w.x, w.y, w.z, w.w};
            #pragma unroll
            for (int e = 0; e < 4; e++) {
                int col = n4*4 + e;
                __nv_bfloat16 h = __float2bfloat16(ws4[e]);
                __nv_bfloat16 l = __float2bfloat16(ws4[e] - __bfloat162float(h));
                Wh[col*PP + kk] = h;
                Wl[col*PP + kk] = l;
            }
        }
        __syncthreads();

        #pragma unroll
        for (int ks = 0; ks < 4; ks++) {
            uint32_t afh[4], afl[4];
            ldsm_x4(afh[0], afh[1], afh[2], afh[3], smem_u32(&Xh[arow*PP + ks*16 + acol]));
            ldsm_x4(afl[0], afl[1], afl[2], afl[3], smem_u32(&Xl[arow*PP + ks*16 + acol]));
            #pragma unroll
            for (int jj = 0; jj < 8; jj += 2) {
                uint32_t bh0,bh1,bh2,bh3, bl0,bl1,bl2,bl3;
                ldsm_x4(bh0,bh1,bh2,bh3, smem_u32(&Wh[(jj*8 + brow)*PP + ks*16 + bcol]));
                ldsm_x4(bl0,bl1,bl2,bl3, smem_u32(&Wl[(jj*8 + brow)*PP + ks*16 + bcol]));
                mma16816(cacc[jj],   afh, bh0, bh1);
                mma16816(cacc[jj],   afh, bl0, bl1);
                mma16816(cacc[jj],   afl, bh0, bh1);
                mma16816(cacc[jj+1], afh, bh2, bh3);
                mma16816(cacc[jj+1], afh, bl2, bl3);
                mma16816(cacc[jj+1], afl, bh2, bh3);
            }
        }
    }

    // ---- epilogue ----
    const int cc = (lane & 3) * 2;
    #pragma unroll
    for (int j = 0; j < 8; j++) {
        float b0 = bias[j*8 + cc], b1 = bias[j*8 + cc + 1];
        cacc[j][0] += b0; cacc[j][1] += b1;
        cacc[j][2] += b0; cacc[j][3] += b1;
    }

    if (which < 2) {
        float ss0 = 0.f, ss1 = 0.f;
        #pragma unroll
        for (int j = 0; j < 8; j++) {
            ss0 += cacc[j][0]*cacc[j][0] + cacc[j][1]*cacc[j][1];
            ss1 += cacc[j][2]*cacc[j][2] + cacc[j][3]*cacc[j][3];
        }
        ss0 += __shfl_xor_sync(0xffffffffu, ss0, 1);
        ss0 += __shfl_xor_sync(0xffffffffu, ss0, 2);
        ss1 += __shfl_xor_sync(0xffffffffu, ss1, 1);
        ss1 += __shfl_xor_sync(0xffffffffu, ss1, 2);
        float sc0 = rsqrtf(ss0), sc1 = rsqrtf(ss1);
        if (which == 0) { sc0 *= 0.125f; sc1 *= 0.125f; }

        __nv_bfloat16* gh = (which == 0) ? g_qh : g_kh;
        __nv_bfloat16* gl = (which == 0) ? g_ql : g_kl;
        const int r0 = rowblock + warp*16 + (lane >> 2);
        const int r1 = r0 + 8;
        #pragma unroll
        for (int j = 0; j < 8; j++) {
            uint32_t hp, lp;
            split2(cacc[j][0]*sc0, cacc[j][1]*sc0, hp, lp);
            *(uint32_t*)&gh[(size_t)r0*DH + j*8 + cc] = hp;
            *(uint32_t*)&gl[(size_t)r0*DH + j*8 + cc] = lp;
            split2(cacc[j][2]*sc1, cacc[j][3]*sc1, hp, lp);
            *(uint32_t*)&gh[(size_t)r1*DH + j*8 + cc] = hp;
            *(uint32_t*)&gl[(size_t)r1*DH + j*8 + cc] = lp;
        }
    } else {
        // V: transpose through smem, then coalesced [b][d][s] store
        __syncthreads();
        __nv_bfloat16* Th = (__nv_bfloat16*)psm;        // 64 x TP
        __nv_bfloat16* Tl = Th + 64*TP;
        const int r0 = warp*16 + (lane >> 2);
        const int r1 = r0 + 8;
        #pragma unroll
        for (int j = 0; j < 8; j++) {
            #pragma unroll
            for (int e = 0; e < 2; e++) {
                int col = j*8 + cc + e;
                float v0 = cacc[j][e], v1 = cacc[j][2+e];
                __nv_bfloat16 h0 = __float2bfloat16(v0);
                __nv_bfloat16 h1 = __float2bfloat16(v1);
                Th[col*TP + r0] = h0;
                Th[col*TP + r1] = h1;
                Tl[col*TP + r0] = __float2bfloat16(v0 - __bfloat162float(h0));
                Tl[col*TP + r1] = __float2bfloat16(v1 - __bfloat162float(h1));
            }
        }
        __syncthreads();
        const int bb = rowblock >> 11;
        const int s0 = rowblock & (S - 1);
        #pragma unroll
        for (int i = 0; i < 4; i++) {
            int idx = tid + i*256;          // 64 cols x 16 uint4
            int col = idx >> 4, u = idx & 15;
            size_t g = ((size_t)bb*DH + col)*S + s0 + u*8;
            *(uint4*)&g_vh[g] = *(uint4*)&Th[col*TP + u*8];
            *(uint4*)&g_vl[g] = *(uint4*)&Tl[col*TP + u*8];
        }
    }
}

// ============================================================
// mma.sync flash attention (bf16x3): CTA = 64 queries (4 warps x m16),
// 128 threads, grid 256 CTAs (32 q-tiles x 8 batches) -> every SM busy,
// 2 CTAs/SM. Keys in 64-tiles; p=exp(s) (bounded cosine scores, no max);
// P accumulators repacked in-register as A-frags; O += P.V.
// ============================================================
#define TPITCH 72
__global__ __launch_bounds__(128) void attn_kernel(float* __restrict__ out)
{
    __shared__ __nv_bfloat16 TS[4 * 64 * TPITCH];   // 36864 B

    const int tid = threadIdx.x;
    const int warp = tid >> 5;       // 0..3
    const int lane = tid & 31;
    const int b = blockIdx.y;
    const int q0 = blockIdx.x * 64;

    const int R = 64 * TPITCH;
    __nv_bfloat16* Kh = TS;
    __nv_bfloat16* Kl = TS + R;
    __nv_bfloat16* Vh = TS + 2*R;
    __nv_bfloat16* Vl = TS + 3*R;

    // ---- Q phase: stage hi (region 0) / lo (region 2), load A-frags ----
    {
        const uint4* qh_g = (const uint4*)(g_qh + ((size_t)b*S + q0)*DH);
        const uint4* ql_g = (const uint4*)(g_ql + ((size_t)b*S + q0)*DH);
        #pragma unroll
        for (int i = 0; i < 4; i++) {
            int idx = tid + i*128;          // 0..511 (64 rows x 8 uint4)
            int r = idx >> 3, c = idx & 7;
            *(uint4*)&TS[r*TPITCH + c*8]       = qh_g[idx];
            *(uint4*)&TS[2*R + r*TPITCH + c*8] = ql_g[idx];
        }
    }
    __syncthreads();

    uint32_t qfh[4][4], qfl[4][4];
    {
        const int arow = warp*16 + (lane & 15);
        const int acol = (lane >> 4) * 8;
        #pragma unroll
        for (int k = 0; k < 4; k++) {
            ldsm_x4(qfh[k][0], qfh[k][1], qfh[k][2], qfh[k][3],
                    smem_u32(&TS[arow*TPITCH + k*16 + acol]));
            ldsm_x4(qfl[k][0], qfl[k][1], qfl[k][2], qfl[k][3],
                    smem_u32(&TS[2*R + arow*TPITCH + k*16 + acol]));
        }
    }

    float oacc[8][4];
    #pragma unroll
    for (int j = 0; j < 8; j++)
        #pragma unroll
        for (int i = 0; i < 4; i++) oacc[j][i] = 0.f;
    float lsum0 = 0.f, lsum1 = 0.f;

    const int brow = (lane & 7) | ((lane & 16) >> 1);
    const int bcol = (lane & 8);

    const uint4* kh_g = (const uint4*)(g_kh + (size_t)b*S*DH);
    const uint4* kl_g = (const uint4*)(g_kl + (size_t)b*S*DH);
    const __nv_bfloat16* vh_g = g_vh + (size_t)b*DH*S;
    const __nv_bfloat16* vl_g = g_vl + (size_t)b*DH*S;

    for (int kt = 0; kt < S/64; kt++) {
        const int key0 = kt * 64;
        __syncthreads();
        #pragma unroll
        for (int i = 0; i < 4; i++) {
            int idx = tid + i*128;          // 0..511
            int r = idx >> 3, c = idx & 7;
            *(uint4*)&Kh[r*TPITCH + c*8] = kh_g[(size_t)(key0 + r)*8 + c];
            *(uint4*)&Kl[r*TPITCH + c*8] = kl_g[(size_t)(key0 + r)*8 + c];
            *(uint4*)&Vh[r*TPITCH + c*8] = *(const uint4*)(vh_g + (size_t)r*S + key0 + c*8);
            *(uint4*)&Vl[r*TPITCH + c*8] = *(const uint4*)(vl_g + (size_t)r*S + key0 + c*8);
        }
        __syncthreads();

        // ---- S = Q.K^T ----
        float sacc[8][4];
        #pragma unroll
        for (int j = 0; j < 8; j++)
            #pragma unroll
            for (int i = 0; i < 4; i++) sacc[j][i] = 0.f;

        #pragma unroll
        for (int k = 0; k < 4; k++) {
            #pragma unroll
            for (int jj = 0; jj < 8; jj += 2) {
                uint32_t bh0,bh1,bh2,bh3, bl0,bl1,bl2,bl3;
                ldsm_x4(bh0,bh1,bh2,bh3, smem_u32(&Kh[(jj*8 + brow)*TPITCH + k*16 + bcol]));
                ldsm_x4(bl0,bl1,bl2,bl3, smem_u32(&Kl[(jj*8 + brow)*TPITCH + k*16 + bcol]));
                mma16816(sacc[jj],   qfh[k], bh0, bh1);
                mma16816(sacc[jj],   qfh[k], bl0, bl1);
                mma16816(sacc[jj],   qfl[k], bh0, bh1);
                mma16816(sacc[jj+1], qfh[k], bh2, bh3);
                mma16816(sacc[jj+1], qfh[k], bl2, bl3);
                mma16816(sacc[jj+1], qfl[k], bh2, bh3);
            }
        }

        // ---- p = exp(s); repack as A-frags hi/lo ----
        uint32_t pfh[4][4], pfl[4][4];
        #pragma unroll
        for (int j = 0; j < 8; j++) {
            float p0 = __expf(sacc[j][0]);
            float p1 = __expf(sacc[j][1]);
            float p2 = __expf(sacc[j][2]);
            float p3 = __expf(sacc[j][3]);
            lsum0 += p0 + p1;
            lsum1 += p2 + p3;
            float h0 = __bfloat162float(__float2bfloat16(p0));
            float h1 = __bfloat162float(__float2bfloat16(p1));
            float h2 = __bfloat162float(__float2bfloat16(p2));
            float h3 = __bfloat162float(__float2bfloat16(p3));
            int kk = j >> 1, o = (j & 1) * 2;
            pfh[kk][o]   = bf2_pack(h0, h1);
            pfh[kk][o+1] = bf2_pack(h2, h3);
            pfl[kk][o]   = bf2_pack(p0 - h0, p1 - h1);
            pfl[kk][o+1] = bf2_pack(p2 - h2, p3 - h3);
        }

        // ---- O += P.V ----
        #pragma unroll
        for (int kk = 0; kk < 4; kk++) {
            #pragma unroll
            for (int jj = 0; jj < 8; jj += 2) {
                uint32_t vh0,vh1,vh2,vh3, vl0,vl1,vl2,vl3;
                ldsm_x4(vh0,vh1,vh2,vh3, smem_u32(&Vh[(jj*8 + brow)*TPITCH + kk*16 + bcol]));
                ldsm_x4(vl0,vl1,vl2,vl3, smem_u32(&Vl[(jj*8 + brow)*TPITCH + kk*16 + bcol]));
                mma16816(oacc[jj],   pfh[kk], vh0, vh1);
                mma16816(oacc[jj],   pfh[kk], vl0, vl1);
                mma16816(oacc[jj],   pfl[kk], vh0, vh1);
                mma16816(oacc[jj+1], pfh[kk], vh2, vh3);
                mma16816(oacc[jj+1], pfh[kk], vl2, vl3);
                mma16816(oacc[jj+1], pfl[kk], vh2, vh3);
            }
        }
    }

    // ---- epilogue ----
    lsum0 += __shfl_xor_sync(0xffffffffu, lsum0, 1);
    lsum0 += __shfl_xor_sync(0xffffffffu, lsum0, 2);
    lsum1 += __shfl_xor_sync(0xffffffffu, lsum1, 1);
    lsum1 += __shfl_xor_sync(0xffffffffu, lsum1, 2);
    const float inv0 = 1.0f / lsum0;
    const float inv1 = 1.0f / lsum1;

    const int r0 = q0 + warp*16 + (lane >> 2);
    const int cc = (lane & 3) * 2;
    float* o0 = out + ((size_t)b*S + r0)*DH + cc;
    float* o1 = o0 + 8*DH;
    #pragma unroll
    for (int j = 0; j < 8; j++) {
        *(float2*)(o0 + j*8) = make_float2(oacc[j][0]*inv0, oacc[j][1]*inv0);
        *(float2*)(o1 + j*8) = make_float2(oacc[j][2]*inv1, oacc[j][3]*inv1);
    }
}

// ============================================================
extern "C" void kernel_launch(void* const* d_in, const int* in_sizes, int n_in,
                              void* d_out, int out_size)
{
    const float* query = (const float*)d_in[0];
    const float* key   = (const float*)d_in[1];
    const float* value = (const float*)d_in[2];
    const float* Wq    = (const float*)d_in[3];
    const float* bq    = (const float*)d_in[4];
    const float* Wk    = (const float*)d_in[5];
    const float* bk    = (const float*)d_in[6];
    const float* Wv    = (const float*)d_in[7];
    const float* bv    = (const float*)d_in[8];
    float* out = (float*)d_out;

    cudaFuncSetAttribute(proj_kernel,
                         cudaFuncAttributeMaxDynamicSharedMemorySize, PROJ_SMEM);

    dim3 pgrid(NROWS / 128, 3);
    proj_kernel<<<pgrid, 256, PROJ_SMEM>>>(query, key, value, Wq, bq, Wk, bk, Wv, bv);

    dim3 agrid(S / 64, B);    // 32 x 8 = 256 CTAs
    attn_kernel<<<agrid, 128>>>(out);
}